// round 8
// baseline (speedup 1.0000x reference)
#include <cuda_runtime.h>
#include <cstdint>
#include <math.h>

// Problem constants
#define B_  8
#define S_  2048
#define T_  128
#define BS_ (B_*S_)

#define RST 144                 // padded s8 tile row stride bytes (128 data + 16 pad)
#define TILE8 (128*RST)         // 18432 bytes per 128x128 s8 tile

// Quantization: x ~= (x1*254 + x0)/Q, x1,x0 in s8
#define QH 31750.0f
#define STMAX 0.08838834764831845f          // 1/sqrt(128), |W| bound
#define QW (QH / STMAX)

// ---------------------------------------------------------------------------
// Device scratch (__device__ globals: allocation-free rule)
// ---------------------------------------------------------------------------
__device__ char  g_B1[128 * TILE8];         // per p: digit1 of W[:,p,:]
__device__ char  g_B0[128 * TILE8];         // per p: digit0
__device__ float g_tokT[(size_t)B_ * T_ * S_];  // tok transposed [b][p][s]
__device__ float g_base[T_];

// ---------------------------------------------------------------------------
// SMEM layout (bytes)
// ---------------------------------------------------------------------------
#define SM_A1 0
#define SM_A0 TILE8
#define STAGE_BYTES (2*TILE8 + 512)              // B1 + B0 + tok column
#define SM_BS(s) (2*TILE8 + (s)*STAGE_BYTES)
#define SM_BC (2*TILE8 + 3*STAGE_BYTES)          // b_comp[128]
#define SM_TB (SM_BC + 512)                      // tanh(b_comp)[128]
#define SMEM_TOTAL (SM_TB + 512)                 // 150,016

// ---------------------------------------------------------------------------
// PTX helpers (sm_80-era: compile for base sm_103 target)
// ---------------------------------------------------------------------------
__device__ __forceinline__ uint32_t smem_u32(const void* p) {
    uint32_t a;
    asm("{ .reg .u64 t; cvta.to.shared.u64 t, %1; cvt.u32.u64 %0, t; }" : "=r"(a) : "l"(p));
    return a;
}
__device__ __forceinline__ void cp16(uint32_t dst, const void* src) {
    asm volatile("cp.async.cg.shared.global [%0], [%1], 16;" :: "r"(dst), "l"(src) : "memory");
}
__device__ __forceinline__ void cp_commit() {
    asm volatile("cp.async.commit_group;" ::: "memory");
}
__device__ __forceinline__ void cp_wait2() {
    asm volatile("cp.async.wait_group 2;" ::: "memory");
}
__device__ __forceinline__ void ldsm4(uint32_t* r, uint32_t addr) {
    asm volatile("ldmatrix.sync.aligned.m8n8.x4.shared.b16 {%0,%1,%2,%3}, [%4];"
        : "=r"(r[0]), "=r"(r[1]), "=r"(r[2]), "=r"(r[3]) : "r"(addr));
}
__device__ __forceinline__ void mma_s8(int* d, const uint32_t* a, const uint32_t* b) {
    asm volatile(
        "mma.sync.aligned.m16n8k32.row.col.s32.s8.s8.s32 "
        "{%0,%1,%2,%3}, {%4,%5,%6,%7}, {%8,%9}, {%0,%1,%2,%3};"
        : "+r"(d[0]), "+r"(d[1]), "+r"(d[2]), "+r"(d[3])
        : "r"(a[0]), "r"(a[1]), "r"(a[2]), "r"(a[3]), "r"(b[0]), "r"(b[1]));
}
__device__ __forceinline__ uint32_t pack4(int a, int b, int c, int d) {
    return (uint32_t)(a & 0xFF) | ((uint32_t)(b & 0xFF) << 8) |
           ((uint32_t)(c & 0xFF) << 16) | ((uint32_t)(d & 0xFF) << 24);
}
// split v (|v| <= 32131) into digits d1*254 + d0, both in [-128,127]
__device__ __forceinline__ void dig(int v, int& d1, int& d0) {
    d1 = __float2int_rn((float)v * (1.0f / 254.0f));
    d0 = v - d1 * 254;
}

// ---------------------------------------------------------------------------
// Prep: W[t][p][q] -> s8 digit tiles g_B1/g_B0[p][t-row 144B]
// ---------------------------------------------------------------------------
__global__ void k_prep_W(const float* __restrict__ W) {
    int p = blockIdx.x;
    char* b1 = g_B1 + (size_t)p * TILE8;
    char* b0 = g_B0 + (size_t)p * TILE8;
    for (int i = threadIdx.x; i < 4096; i += 256) {
        int t = i >> 5, q0 = (i & 31) * 4;
        const float* wr = W + (size_t)t * 16384 + p * 128 + q0;
        float4 w = *(const float4*)wr;
        int v0 = __float2int_rn(w.x * QW), v1 = __float2int_rn(w.y * QW);
        int v2 = __float2int_rn(w.z * QW), v3 = __float2int_rn(w.w * QW);
        int h0, l0, h1, l1, h2, l2, h3, l3;
        dig(v0, h0, l0); dig(v1, h1, l1); dig(v2, h2, l2); dig(v3, h3, l3);
        *(uint32_t*)(b1 + t * RST + q0) = pack4(h0, h1, h2, h3);
        *(uint32_t*)(b0 + t * RST + q0) = pack4(l0, l1, l2, l3);
    }
}

// tok [b][s][p] -> g_tokT [b][p][s]
__global__ void k_prep_tokT(const float* __restrict__ tok) {
    __shared__ float tile[32][33];
    int b = blockIdx.z;
    int sblk = blockIdx.x * 32, pblk = blockIdx.y * 32;
    int tx = threadIdx.x, ty = threadIdx.y;
    #pragma unroll
    for (int i = ty; i < 32; i += 8)
        tile[i][tx] = tok[((size_t)b * S_ + sblk + i) * T_ + pblk + tx];
    __syncthreads();
    #pragma unroll
    for (int i = ty; i < 32; i += 8)
        g_tokT[((size_t)b * T_ + pblk + i) * S_ + sblk + tx] = tile[tx][i];
}

__global__ void k_compute_base(const float* __restrict__ w_red,
                               const float* __restrict__ b_red,
                               const float* __restrict__ b_comp) {
    __shared__ float sbuf[256];
    int tid = threadIdx.x;
    float s = 0.f;
    for (int i = tid; i < S_; i += 256) s += w_red[i];
    sbuf[tid] = s;
    __syncthreads();
    for (int st = 128; st > 0; st >>= 1) {
        if (tid < st) sbuf[tid] += sbuf[tid + st];
        __syncthreads();
    }
    if (tid < T_) g_base[tid] = sbuf[0] * tanhf(b_comp[tid]) + b_red[0];
}

__global__ void k_fill_out(float4* __restrict__ out4) {
    int i = blockIdx.x * 256 + threadIdx.x;
    if (i < BS_ * T_ / 4) {
        const float4* b4 = (const float4*)g_base;
        out4[i] = b4[i & 31];
    }
}

// ---------------------------------------------------------------------------
// Main: 128 CTAs x 512 threads; CTA = 128 token rows x 128 t cols.
// Warp tile 32m x 32n. Static A digits in SMEM; per p, B digits via cp.async.
//   acc1 = A1*B1,  acc2 = A1*B0 + A0*B1,  gi = 254*acc1 + acc2
//   val[m,t] += tok[m,p] * (float)gi;  final scale KC = 254/(QH*QW)
// ---------------------------------------------------------------------------
__global__ __launch_bounds__(512, 1)
void k_main(const float* __restrict__ tok,
            const int*   __restrict__ heads,
            const float* __restrict__ b_comp,
            const float* __restrict__ w_red,
            float*       __restrict__ out) {
    extern __shared__ char smem[];
    uint32_t sb = smem_u32(smem);
    int tid = threadIdx.x, lane = tid & 31, wid = tid >> 5;
    int bb = blockIdx.x >> 4;
    int s0 = (blockIdx.x & 15) * 128;
    int m0 = (wid & 3) * 32;     // warp m-tile
    int n0 = (wid >> 2) * 32;    // warp n-tile

    if (tid < 128) {
        float bc = b_comp[tid];
        *(float*)(smem + SM_BC + tid * 4) = bc;
        *(float*)(smem + SM_TB + tid * 4) = tanhf(bc);
    }

    // --- build static A digit tiles from tanh(tok tile)
    const float* tokbase = tok + ((size_t)bb * S_ + s0) * T_;
    for (int g = tid; g < 2048; g += 512) {
        int m = g >> 4, q0 = (g & 15) * 8;
        float4 v0 = *(const float4*)(tokbase + m * T_ + q0);
        float4 v1 = *(const float4*)(tokbase + m * T_ + q0 + 4);
        float f[8] = {v0.x, v0.y, v0.z, v0.w, v1.x, v1.y, v1.z, v1.w};
        int d1[8], d0[8];
        #pragma unroll
        for (int j = 0; j < 8; j++) {
            int hq = __float2int_rn(tanhf(f[j]) * QH);
            dig(hq, d1[j], d0[j]);
        }
        uint2 u1, u0;
        u1.x = pack4(d1[0], d1[1], d1[2], d1[3]); u1.y = pack4(d1[4], d1[5], d1[6], d1[7]);
        u0.x = pack4(d0[0], d0[1], d0[2], d0[3]); u0.y = pack4(d0[4], d0[5], d0[6], d0[7]);
        *(uint2*)(smem + SM_A1 + m * RST + q0) = u1;
        *(uint2*)(smem + SM_A0 + m * RST + q0) = u0;
    }

    // --- prologue: 3-stage cp.async pipeline (B digits + tok column)
    #pragma unroll
    for (int pp = 0; pp < 3; pp++) {
        uint32_t dst = sb + SM_BS(pp);
        const char* s1 = g_B1 + (size_t)pp * TILE8;
        const char* s2 = g_B0 + (size_t)pp * TILE8;
        for (int i = tid; i < TILE8 / 16; i += 512) {
            cp16(dst + i * 16, s1 + i * 16);
            cp16(dst + TILE8 + i * 16, s2 + i * 16);
        }
        if (tid < 32)
            cp16(dst + 2 * TILE8 + tid * 16,
                 (const char*)g_tokT + (((size_t)bb * T_ + pp) * S_ + s0) * 4 + tid * 16);
        cp_commit();
    }
    __syncthreads();   // A tiles + bc/tb visible

    // --- lane-fixed ldmatrix address components
    uint32_t aOff = (uint32_t)(m0 + (lane & 15)) * RST + ((lane >> 4) << 4);
    uint32_t aA1 = sb + SM_A1 + aOff;
    uint32_t aA0 = sb + SM_A0 + aOff;
    uint32_t bOff = (uint32_t)(n0 + ((lane >> 4) << 3) + (lane & 7)) * RST
                  + ((lane >> 3) & 1) * 16;

    float val[2][4][4];
    #pragma unroll
    for (int mf = 0; mf < 2; mf++)
        #pragma unroll
        for (int nf = 0; nf < 4; nf++)
            #pragma unroll
            for (int e = 0; e < 4; e++) val[mf][nf][e] = 0.f;

    int s = 0;
    #pragma unroll 1
    for (int p = 0; p < 128; p++) {
        cp_wait2();
        __syncthreads();

        uint32_t bB1 = sb + SM_BS(s) + bOff;
        uint32_t bB0 = bB1 + TILE8;

        int acc1[2][4][4], acc2[2][4][4];
        #pragma unroll
        for (int mf = 0; mf < 2; mf++)
            #pragma unroll
            for (int nf = 0; nf < 4; nf++)
                #pragma unroll
                for (int e = 0; e < 4; e++) { acc1[mf][nf][e] = 0; acc2[mf][nf][e] = 0; }

        #pragma unroll
        for (int ks = 0; ks < 4; ks++) {
            uint32_t ao = ks * 32;
            uint32_t A1f[2][4], A0f[2][4];
            ldsm4(A1f[0], aA1 + ao);
            ldsm4(A1f[1], aA1 + 16 * RST + ao);
            ldsm4(A0f[0], aA0 + ao);
            ldsm4(A0f[1], aA0 + 16 * RST + ao);
            uint32_t B1f[8], B0f[8];
            ldsm4(&B1f[0], bB1 + ao);
            ldsm4(&B1f[4], bB1 + 16 * RST + ao);
            ldsm4(&B0f[0], bB0 + ao);
            ldsm4(&B0f[4], bB0 + 16 * RST + ao);
            #pragma unroll
            for (int mf = 0; mf < 2; mf++)
                #pragma unroll
                for (int nf = 0; nf < 4; nf++) {
                    mma_s8(acc1[mf][nf], A1f[mf], &B1f[nf * 2]);
                    mma_s8(acc2[mf][nf], A1f[mf], &B0f[nf * 2]);
                    mma_s8(acc2[mf][nf], A0f[mf], &B1f[nf * 2]);
                }
        }

        // scale-accumulate: val += tok[m,p] * (254*acc1 + acc2)
        const float* tcol = (const float*)(smem + SM_BS(s) + 2 * TILE8);
        int rb = m0 + (lane >> 2);
        float tv[4];
        tv[0] = tcol[rb];      tv[1] = tcol[rb + 8];
        tv[2] = tcol[rb + 16]; tv[3] = tcol[rb + 24];
        #pragma unroll
        for (int mf = 0; mf < 2; mf++)
            #pragma unroll
            for (int nf = 0; nf < 4; nf++)
                #pragma unroll
                for (int e = 0; e < 4; e++) {
                    int gi = acc1[mf][nf][e] * 254 + acc2[mf][nf][e];
                    val[mf][nf][e] = fmaf(tv[mf * 2 + (e >> 1)], (float)gi, val[mf][nf][e]);
                }

        __syncthreads();   // all warps done with stage s before overwrite

        if (p + 3 < 128) {
            uint32_t dst = sb + SM_BS(s);
            const char* s1 = g_B1 + (size_t)(p + 3) * TILE8;
            const char* s2 = g_B0 + (size_t)(p + 3) * TILE8;
            for (int i = tid; i < TILE8 / 16; i += 512) {
                cp16(dst + i * 16, s1 + i * 16);
                cp16(dst + TILE8 + i * 16, s2 + i * 16);
            }
            if (tid < 32)
                cp16(dst + 2 * TILE8 + tid * 16,
                     (const char*)g_tokT + (((size_t)bb * T_ + p + 3) * S_ + s0) * 4 + tid * 16);
        }
        cp_commit();
        if (++s == 3) s = 0;
    }

    // --- epilogue: act = tanh(KC*val + bc); scatter w_red*(act - tanh(bc))
    const float KC = (float)(254.0 / ((double)QH * (double)QW));
    const float* bcv = (const float*)(smem + SM_BC);
    const float* tbv = (const float*)(smem + SM_TB);
    int r0 = m0 + (lane >> 2);
    #pragma unroll
    for (int mf = 0; mf < 2; mf++)
        #pragma unroll
        for (int eh = 0; eh < 2; eh++) {
            int row = r0 + mf * 16 + eh * 8;
            int srow = s0 + row;
            float wr = w_red[srow];
            int hd = heads[bb * S_ + srow];
            float* orow = out + ((size_t)bb * S_ + hd) * T_;
            #pragma unroll
            for (int nf = 0; nf < 4; nf++)
                #pragma unroll
                for (int ec = 0; ec < 2; ec++) {
                    int col = n0 + nf * 8 + (lane & 3) * 2 + ec;
                    float act = tanhf(val[mf][nf][eh * 2 + ec] * KC + bcv[col]);
                    atomicAdd(orow + col, wr * (act - tbv[col]));
                }
        }
}

// ---------------------------------------------------------------------------
extern "C" void kernel_launch(void* const* d_in, const int* in_sizes, int n_in,
                              void* d_out, int out_size) {
    (void)in_sizes; (void)n_in; (void)out_size;
    const float* tok    = (const float*)d_in[0];
    // d_in[1] = dep_embeddings: dead input (source bug), unused
    const int*   heads  = (const int*)  d_in[2];
    const float* W      = (const float*)d_in[3];
    const float* b_comp = (const float*)d_in[4];
    const float* w_red  = (const float*)d_in[5];
    const float* b_red  = (const float*)d_in[6];
    float* out = (float*)d_out;

    cudaFuncSetAttribute(k_main, cudaFuncAttributeMaxDynamicSharedMemorySize, SMEM_TOTAL);

    k_prep_W<<<128, 256>>>(W);
    k_prep_tokT<<<dim3(64, 4, 8), dim3(32, 8)>>>(tok);
    k_compute_base<<<1, 256>>>(w_red, b_red, b_comp);
    k_fill_out<<<4096, 256>>>((float4*)out);
    k_main<<<128, 512, SMEM_TOTAL>>>(tok, heads, b_comp, w_red, out);
}